// round 1
// baseline (speedup 1.0000x reference)
#include <cuda_runtime.h>
#include <math.h>
#include <stdint.h>

#define E_NN 50000
#define F_NN 25000
#define M_NN 100000
#define P_NN 75000
#define DD   128
#define HDD  384

// ---------------- scratch (device globals; no allocation allowed) ----------------
__device__ float g_h0[F_NN * DD];
__device__ float g_h1[F_NN * DD];
__device__ float g_haggr[F_NN * DD];
__device__ float g_ea[P_NN * DD];
__device__ float g_eattr[M_NN * DD];
__device__ float g_q[E_NN * HDD];
__device__ float g_k[F_NN * HDD];
__device__ float g_v[F_NN * HDD];
__device__ float g_ep[M_NN * HDD];
__device__ float g_alpha[M_NN * 3];
__device__ float g_amax[E_NN * 3];
__device__ float g_den[E_NN * 3];
__device__ float g_seg[E_NN * HDD];

// ---------------- small utility kernels ----------------
__global__ void fill_kernel(float* __restrict__ p, int n, float v) {
    int t = blockIdx.x * blockDim.x + threadIdx.x;
    if (t < n) p[t] = v;
}

__device__ __forceinline__ void atomicMaxFloat(float* addr, float val) {
    int* ia = (int*)addr;
    int old = *ia;
    while (val > __int_as_float(old)) {
        int assumed = old;
        old = atomicCAS(ia, assumed, __float_as_int(val));
        if (old == assumed) break;
    }
}

// h_aggr[f] += h_dE[e] * sgn  over cobdry edges. One warp per edge.
__global__ void scatter_aggr_kernel(const float* __restrict__ hE,
                                    const int* __restrict__ cob,
                                    float* __restrict__ haggr) {
    int t = blockIdx.x * blockDim.x + threadIdx.x;
    int e = t >> 5;
    if (e >= M_NN) return;
    int lane = t & 31;
    int ecol = cob[e * 3 + 0];
    int fcol = cob[e * 3 + 1];
    float s = (float)cob[e * 3 + 2];
    float4 v4 = ((const float4*)(hE + (size_t)ecol * DD))[lane];
    float* o = haggr + (size_t)fcol * DD + lane * 4;
    atomicAdd(o + 0, s * v4.x);
    atomicAdd(o + 1, s * v4.y);
    atomicAdd(o + 2, s * v4.z);
    atomicAdd(o + 3, s * v4.w);
}

// out[i][:] = src[idx[i*3+idxcol]][:]  (optionally * sign from signcol)
__global__ void gather_rows_kernel(const float* __restrict__ src,
                                   const int* __restrict__ idx,
                                   float* __restrict__ out,
                                   int E, int idxcol, int signcol) {
    int t = blockIdx.x * blockDim.x + threadIdx.x;
    int e = t >> 5;
    if (e >= E) return;
    int lane = t & 31;
    int r = idx[e * 3 + idxcol];
    float s = (signcol >= 0) ? (float)idx[e * 3 + signcol] : 1.0f;
    float4 v4 = ((const float4*)(src + (size_t)r * DD))[lane];
    v4.x *= s; v4.y *= s; v4.z *= s; v4.w *= s;
    ((float4*)(out + (size_t)e * DD))[lane] = v4;
}

// ---------------- GEMM: C[M,N] = A[M,128] @ B[128,N] (+bias) (+=C) ----------------
// BM=BN=128, BK=16, 256 threads, 8x8 microtile.
__global__ __launch_bounds__(256) void gemm_k128(
    const float* __restrict__ A, const float* __restrict__ B,
    const float* __restrict__ bias, float* __restrict__ C,
    int M, int N, int accum)
{
    __shared__ float As[16][128];
    __shared__ float Bs[16][128];
    const int tid = threadIdx.x;
    const int row0 = blockIdx.y * 128;
    const int col0 = blockIdx.x * 128;
    const int tx = tid & 15;
    const int ty = tid >> 4;

    float acc[8][8];
#pragma unroll
    for (int i = 0; i < 8; i++)
#pragma unroll
        for (int j = 0; j < 8; j++) acc[i][j] = 0.f;

    const int a_row = tid >> 2;        // 0..63
    const int a_k = (tid & 3) << 2;    // 0,4,8,12
    const int b_k = tid >> 5;          // 0..7
    const int b_col = (tid & 31) << 2; // 0..124

    for (int k0 = 0; k0 < 128; k0 += 16) {
#pragma unroll
        for (int i = 0; i < 2; i++) {
            int r = a_row + i * 64;
            int gr = row0 + r;
            float4 va = make_float4(0.f, 0.f, 0.f, 0.f);
            if (gr < M) va = *(const float4*)(A + (size_t)gr * 128 + k0 + a_k);
            As[a_k + 0][r] = va.x;
            As[a_k + 1][r] = va.y;
            As[a_k + 2][r] = va.z;
            As[a_k + 3][r] = va.w;
        }
#pragma unroll
        for (int i = 0; i < 2; i++) {
            int kk = b_k + i * 8;
            *(float4*)&Bs[kk][b_col] =
                *(const float4*)(B + (size_t)(k0 + kk) * N + col0 + b_col);
        }
        __syncthreads();
#pragma unroll
        for (int kk = 0; kk < 16; kk++) {
            float a[8], b[8];
            *(float4*)&a[0] = *(const float4*)&As[kk][ty * 4];
            *(float4*)&a[4] = *(const float4*)&As[kk][64 + ty * 4];
            *(float4*)&b[0] = *(const float4*)&Bs[kk][tx * 4];
            *(float4*)&b[4] = *(const float4*)&Bs[kk][64 + tx * 4];
#pragma unroll
            for (int i = 0; i < 8; i++)
#pragma unroll
                for (int j = 0; j < 8; j++)
                    acc[i][j] = fmaf(a[i], b[j], acc[i][j]);
        }
        __syncthreads();
    }

#pragma unroll
    for (int i = 0; i < 8; i++) {
        int r = row0 + ((i < 4) ? (ty * 4 + i) : (64 + ty * 4 + (i - 4)));
        if (r >= M) continue;
#pragma unroll
        for (int jj = 0; jj < 2; jj++) {
            int c = col0 + ((jj == 0) ? (tx * 4) : (64 + tx * 4));
            float4 res;
            res.x = acc[i][jj * 4 + 0];
            res.y = acc[i][jj * 4 + 1];
            res.z = acc[i][jj * 4 + 2];
            res.w = acc[i][jj * 4 + 3];
            if (bias) {
                res.x += bias[c + 0];
                res.y += bias[c + 1];
                res.z += bias[c + 2];
                res.w += bias[c + 3];
            }
            float* cp = C + (size_t)r * N + c;
            if (accum) {
                float4 old = *(float4*)cp;
                res.x += old.x; res.y += old.y; res.z += old.z; res.w += old.w;
            }
            *(float4*)cp = res;
        }
    }
}

// ---------------- attention kernels ----------------
// alpha[e,h] = dot(q[dst,h,:], k[src,h,:] + ep[e,h,:]) / sqrt(128); also amax via atomicMax.
__global__ void attn_alpha_kernel(const float* __restrict__ q,
                                  const float* __restrict__ k,
                                  const float* __restrict__ ep,
                                  const int* __restrict__ idx,
                                  int srcCol, int dstCol, int E,
                                  float* __restrict__ alpha,
                                  float* __restrict__ amax) {
    int e = blockIdx.x * 8 + (threadIdx.x >> 5);
    if (e >= E) return;
    int lane = threadIdx.x & 31;
    int src = idx[e * 3 + srcCol];
    int dst = idx[e * 3 + dstCol];
    const float4* qp = (const float4*)(q + (size_t)dst * HDD);
    const float4* kp = (const float4*)(k + (size_t)src * HDD);
    const float4* epp = (const float4*)(ep + (size_t)e * HDD);
#pragma unroll
    for (int h = 0; h < 3; h++) {
        float4 qv = qp[h * 32 + lane];
        float4 kv = kp[h * 32 + lane];
        float4 ev = epp[h * 32 + lane];
        float s = qv.x * (kv.x + ev.x) + qv.y * (kv.y + ev.y) +
                  qv.z * (kv.z + ev.z) + qv.w * (kv.w + ev.w);
#pragma unroll
        for (int o = 16; o > 0; o >>= 1) s += __shfl_xor_sync(0xffffffffu, s, o);
        if (lane == 0) {
            s *= 0.08838834764831845f;  // 1/sqrt(128)
            alpha[e * 3 + h] = s;
            atomicMaxFloat(&amax[dst * 3 + h], s);
        }
    }
}

__global__ void attn_expden_kernel(const int* __restrict__ idx, int dstCol, int E,
                                   float* __restrict__ alpha,
                                   const float* __restrict__ amax,
                                   float* __restrict__ den) {
    int t = blockIdx.x * blockDim.x + threadIdx.x;
    if (t >= E * 3) return;
    int e = t / 3, h = t - 3 * e;
    int dst = idx[e * 3 + dstCol];
    float ex = expf(alpha[t] - amax[dst * 3 + h]);
    alpha[t] = ex;
    atomicAdd(&den[dst * 3 + h], ex);
}

// seg[dst,h,:] += (alpha/den) * (v[src,h,:] + ep[e,h,:])
__global__ void attn_scatter_kernel(const float* __restrict__ v,
                                    const float* __restrict__ ep,
                                    const int* __restrict__ idx,
                                    int srcCol, int dstCol, int E,
                                    const float* __restrict__ alpha,
                                    const float* __restrict__ den,
                                    float* __restrict__ seg) {
    int e = blockIdx.x * 8 + (threadIdx.x >> 5);
    if (e >= E) return;
    int lane = threadIdx.x & 31;
    int src = idx[e * 3 + srcCol];
    int dst = idx[e * 3 + dstCol];
    const float4* vp = (const float4*)(v + (size_t)src * HDD);
    const float4* epp = (const float4*)(ep + (size_t)e * HDD);
    float* op = seg + (size_t)dst * HDD;
#pragma unroll
    for (int h = 0; h < 3; h++) {
        float w = alpha[e * 3 + h] / (den[dst * 3 + h] + 1e-16f);
        float4 vv = vp[h * 32 + lane];
        float4 ev = epp[h * 32 + lane];
        int c = h * 128 + lane * 4;
        atomicAdd(op + c + 0, w * (vv.x + ev.x));
        atomicAdd(op + c + 1, w * (vv.y + ev.y));
        atomicAdd(op + c + 2, w * (vv.z + ev.z));
        atomicAdd(op + c + 3, w * (vv.w + ev.w));
    }
}

// out = mean over heads (+ optional residual hin)
__global__ void combine_kernel(const float* __restrict__ seg,
                               const float* __restrict__ hin,
                               float* __restrict__ out, int n) {
    int t = blockIdx.x * blockDim.x + threadIdx.x;
    if (t >= n * DD) return;
    int node = t >> 7, d = t & 127;
    const float* s = seg + (size_t)node * HDD;
    float m = (s[d] + s[128 + d] + s[256 + d]) * (1.0f / 3.0f);
    out[t] = hin ? (m + hin[t]) : m;
}

// ---------------- host orchestration ----------------
static inline int cdiv(int a, int b) { return (a + b - 1) / b; }

extern "C" void kernel_launch(void* const* d_in, const int* in_sizes, int n_in,
                              void* d_out, int out_size) {
    const float* h_dE = (const float*)d_in[0];
    const float* h_dF = (const float*)d_in[1];
    const int* cob = (const int*)d_in[2];
    const int* nn = (const int*)d_in[3];
    const float* aggr_W = (const float*)d_in[4];
    const float* aggr_b = (const float*)d_in[5];
    const float* ctr_W = (const float*)d_in[6];
    const float* ctr_b = (const float*)d_in[7];
    const float* f_Wq = (const float*)d_in[8];
    const float* f_bq = (const float*)d_in[9];
    const float* f_Wk = (const float*)d_in[10];
    const float* f_bk = (const float*)d_in[11];
    const float* f_Wv = (const float*)d_in[12];
    const float* f_bv = (const float*)d_in[13];
    const float* f_We = (const float*)d_in[14];
    const float* f_Ws = (const float*)d_in[15];
    const float* f_bs = (const float*)d_in[16];
    const float* e_Wq = (const float*)d_in[17];
    const float* e_bq = (const float*)d_in[18];
    const float* e_Wk = (const float*)d_in[19];
    const float* e_bk = (const float*)d_in[20];
    const float* e_Wv = (const float*)d_in[21];
    const float* e_bv = (const float*)d_in[22];
    const float* e_We = (const float*)d_in[23];
    const float* e_Ws = (const float*)d_in[24];
    const float* e_bs = (const float*)d_in[25];
    float* out = (float*)d_out;

    float *h0, *h1, *haggr, *ea, *eattr, *q, *k, *v, *ep, *alpha, *amax, *den, *seg;
    cudaGetSymbolAddress((void**)&h0, g_h0);
    cudaGetSymbolAddress((void**)&h1, g_h1);
    cudaGetSymbolAddress((void**)&haggr, g_haggr);
    cudaGetSymbolAddress((void**)&ea, g_ea);
    cudaGetSymbolAddress((void**)&eattr, g_eattr);
    cudaGetSymbolAddress((void**)&q, g_q);
    cudaGetSymbolAddress((void**)&k, g_k);
    cudaGetSymbolAddress((void**)&v, g_v);
    cudaGetSymbolAddress((void**)&ep, g_ep);
    cudaGetSymbolAddress((void**)&alpha, g_alpha);
    cudaGetSymbolAddress((void**)&amax, g_amax);
    cudaGetSymbolAddress((void**)&den, g_den);
    cudaGetSymbolAddress((void**)&seg, g_seg);

    const float NEG_INF = -INFINITY;

    // 1) h_aggr = segment_sum(h_dE[e]*sgn over f)
    fill_kernel<<<cdiv(F_NN * DD, 256), 256>>>(haggr, F_NN * DD, 0.f);
    scatter_aggr_kernel<<<cdiv(M_NN * 32, 256), 256>>>(h_dE, cob, haggr);

    // 2) h = h_aggr@aggr_W + aggr_b + h_dF@ctr_W + ctr_b
    {
        dim3 g(1, cdiv(F_NN, 128));
        gemm_k128<<<g, 256>>>(haggr, aggr_W, aggr_b, h0, F_NN, 128, 0);
        gemm_k128<<<g, 256>>>(h_dF, ctr_W, ctr_b, h0, F_NN, 128, 1);
    }

    // 3) ea = h_dE[nn[:,2]]  (constant across layers)
    gather_rows_kernel<<<cdiv(P_NN * 32, 256), 256>>>(h_dE, nn, ea, P_NN, 2, -1);

    float* hcur = h0;
    float* hnext = h1;
    for (int l = 0; l < 3; l++) {
        const float* Wq = f_Wq + (size_t)l * 128 * 384;
        const float* bq = f_bq + (size_t)l * 384;
        const float* Wk = f_Wk + (size_t)l * 128 * 384;
        const float* bk = f_bk + (size_t)l * 384;
        const float* Wv = f_Wv + (size_t)l * 128 * 384;
        const float* bv = f_bv + (size_t)l * 384;
        const float* We = f_We + (size_t)l * 128 * 384;
        const float* Ws = f_Ws + (size_t)l * 128 * 128;
        const float* bs = f_bs + (size_t)l * 128;

        dim3 g3(3, cdiv(F_NN, 128));
        gemm_k128<<<g3, 256>>>(hcur, Wq, bq, q, F_NN, 384, 0);
        gemm_k128<<<g3, 256>>>(hcur, Wk, bk, k, F_NN, 384, 0);
        gemm_k128<<<g3, 256>>>(hcur, Wv, bv, v, F_NN, 384, 0);
        dim3 ge(3, cdiv(P_NN, 128));
        gemm_k128<<<ge, 256>>>(ea, We, nullptr, ep, P_NN, 384, 0);

        fill_kernel<<<cdiv(F_NN * 3, 256), 256>>>(amax, F_NN * 3, NEG_INF);
        fill_kernel<<<cdiv(F_NN * 3, 256), 256>>>(den, F_NN * 3, 0.f);
        fill_kernel<<<cdiv(F_NN * HDD, 256), 256>>>(seg, F_NN * HDD, 0.f);

        attn_alpha_kernel<<<cdiv(P_NN, 8), 256>>>(q, k, ep, nn, 0, 1, P_NN, alpha, amax);
        attn_expden_kernel<<<cdiv(P_NN * 3, 256), 256>>>(nn, 1, P_NN, alpha, amax, den);
        attn_scatter_kernel<<<cdiv(P_NN, 8), 256>>>(v, ep, nn, 0, 1, P_NN, alpha, den, seg);

        combine_kernel<<<cdiv(F_NN * DD, 256), 256>>>(seg, hcur, hnext, F_NN);
        dim3 g1(1, cdiv(F_NN, 128));
        gemm_k128<<<g1, 256>>>(hcur, Ws, bs, hnext, F_NN, 128, 1);

        float* tmp = hcur; hcur = hnext; hnext = tmp;
    }

    // final cross attention: F -> E over cobdry edges (src=f_col(1), dst=e_col(0))
    gather_rows_kernel<<<cdiv(M_NN * 32, 256), 256>>>(hcur, cob, eattr, M_NN, 1, 2);

    {
        dim3 gq(3, cdiv(E_NN, 128));
        gemm_k128<<<gq, 256>>>(h_dE, e_Wq, e_bq, q, E_NN, 384, 0);
        dim3 gk(3, cdiv(F_NN, 128));
        gemm_k128<<<gk, 256>>>(hcur, e_Wk, e_bk, k, F_NN, 384, 0);
        gemm_k128<<<gk, 256>>>(hcur, e_Wv, e_bv, v, F_NN, 384, 0);
        dim3 ge(3, cdiv(M_NN, 128));
        gemm_k128<<<ge, 256>>>(eattr, e_We, nullptr, ep, M_NN, 384, 0);
    }

    fill_kernel<<<cdiv(E_NN * 3, 256), 256>>>(amax, E_NN * 3, NEG_INF);
    fill_kernel<<<cdiv(E_NN * 3, 256), 256>>>(den, E_NN * 3, 0.f);
    fill_kernel<<<cdiv(E_NN * HDD, 256), 256>>>(seg, E_NN * HDD, 0.f);

    attn_alpha_kernel<<<cdiv(M_NN, 8), 256>>>(q, k, ep, cob, 1, 0, M_NN, alpha, amax);
    attn_expden_kernel<<<cdiv(M_NN * 3, 256), 256>>>(cob, 0, M_NN, alpha, amax, den);
    attn_scatter_kernel<<<cdiv(M_NN, 8), 256>>>(v, ep, cob, 1, 0, M_NN, alpha, den, seg);

    combine_kernel<<<cdiv(E_NN * DD, 256), 256>>>(seg, nullptr, out, E_NN);
    {
        dim3 g1(1, cdiv(E_NN, 128));
        gemm_k128<<<g1, 256>>>(h_dE, e_Ws, e_bs, out, E_NN, 128, 1);
    }
}